// round 14
// baseline (speedup 1.0000x reference)
#include <cuda_runtime.h>
#include <cuda_fp16.h>

#define NB 8
#define NT 256   // TE == TD
#define ND 256
#define NU 256

// Scratch (no allocations allowed in kernel_launch)
__device__ __half2 g_aeP[NB*128*NT];  // ae pair-interleaved transposed: [b][u/2][t]
__device__ __half  g_ad_h[NB*NT*NU];  // (B*TD, U) row-major f16
__device__ float g_alphas[NB*NT*NT];  // (B, TD, TE)
__device__ float g_maxmu[NB*NT];      // (B, TD)
__device__ float g_hhat[NB*ND];       // (B, D)

__device__ __forceinline__ __half2 tanh_h2(__half2 h){
    unsigned u = *reinterpret_cast<unsigned*>(&h);
    unsigned r;
    asm("tanh.approx.f16x2 %0, %1;" : "=r"(r) : "r"(u));
    return *reinterpret_cast<__half2*>(&r);
}
__device__ __forceinline__ __half2 as_h2(unsigned u){
    return *reinterpret_cast<__half2*>(&u);
}

__device__ __forceinline__ void cp_async16(void* smem_dst, const void* gsrc){
    unsigned sa = (unsigned)__cvta_generic_to_shared(smem_dst);
    asm volatile("cp.async.cg.shared.global [%0], [%1], 16;\n" :: "r"(sa), "l"(gsrc));
}
__device__ __forceinline__ void cp_async_commit(){ asm volatile("cp.async.commit_group;\n" ::: "memory"); }
__device__ __forceinline__ void cp_async_wait0(){ asm volatile("cp.async.wait_group 0;\n" ::: "memory"); }

// ---------------------------------------------------------------------------
// K1 v7: ae = en @ w_en, ad = de @ w_de. Compute f32 (unchanged mainloop).
// ae blocks: epilogue smem-transposes to g_aeP [b][up][t] (half2).
// ad blocks: row-major f16 store as before.
// ---------------------------------------------------------------------------
__global__ void __launch_bounds__(512) k1_proj(
    const float* __restrict__ en, const float* __restrict__ de,
    const float* __restrict__ w_en, const float* __restrict__ w_de)
{
    extern __shared__ float smem[];
    float*  s_in = smem;                       // 32 rows x 256 = 8192 floats (32KB)
    float4* s_w  = (float4*)(smem + 32*ND);    // [2][32*64] float4 (2x32KB)

    int bb = blockIdx.x;
    bool isA = bb < 64;
    int rb = (isA ? bb : bb - 64) * 32;            // row base in [0,2048)
    const float* in = isA ? en : de;
    const float* w  = isA ? w_en : w_de;
    int tid = threadIdx.x;

    {
        const float4* in4 = (const float4*)(in + rb*ND);
        const float4* w4  = (const float4*)w;
        #pragma unroll
        for (int i = 0; i < 4; i++)
            cp_async16(&((float4*)s_in)[tid + i*512], &in4[tid + i*512]);
        #pragma unroll
        for (int i = 0; i < 4; i++)
            cp_async16(&s_w[tid + i*512], &w4[tid + i*512]);
        cp_async_commit();
        cp_async_wait0();
    }
    __syncthreads();

    const float4* w4 = (const float4*)w;     // flat [d*64 + ug]
    int tx = tid & 63;        // u-group of 4
    int ty = tid >> 6;        // 0..7 -> rows ty*4..ty*4+3 (warp-uniform)
    const float* srow = s_in + ty*4*ND;

    float4 a0 = make_float4(0.f,0.f,0.f,0.f);
    float4 a1 = a0, a2 = a0, a3 = a0;

    for (int st = 0; st < 8; st++){
        int cur = st & 1;
        if (st < 7){
            float4* dst = s_w + (cur^1)*2048;
            const float4* src = w4 + (st+1)*2048;
            #pragma unroll
            for (int i = 0; i < 4; i++)
                cp_async16(&dst[tid + i*512], &src[tid + i*512]);
            cp_async_commit();
        }
        const float4* wst = s_w + cur*2048;
        #pragma unroll 2
        for (int dg = 0; dg < 8; dg++){          // 8 groups of 4 d
            int dbase = st*32 + dg*4;
            float4 x0 = *(const float4*)&srow[0*ND + dbase];
            float4 x1 = *(const float4*)&srow[1*ND + dbase];
            float4 x2 = *(const float4*)&srow[2*ND + dbase];
            float4 x3 = *(const float4*)&srow[3*ND + dbase];
            #pragma unroll
            for (int jj = 0; jj < 4; jj++){
                float4 wv = wst[(dg*4 + jj)*64 + tx];
                float xs0 = (&x0.x)[jj];
                float xs1 = (&x1.x)[jj];
                float xs2 = (&x2.x)[jj];
                float xs3 = (&x3.x)[jj];
                a0.x = fmaf(xs0, wv.x, a0.x); a0.y = fmaf(xs0, wv.y, a0.y);
                a0.z = fmaf(xs0, wv.z, a0.z); a0.w = fmaf(xs0, wv.w, a0.w);
                a1.x = fmaf(xs1, wv.x, a1.x); a1.y = fmaf(xs1, wv.y, a1.y);
                a1.z = fmaf(xs1, wv.z, a1.z); a1.w = fmaf(xs1, wv.w, a1.w);
                a2.x = fmaf(xs2, wv.x, a2.x); a2.y = fmaf(xs2, wv.y, a2.y);
                a2.z = fmaf(xs2, wv.z, a2.z); a2.w = fmaf(xs2, wv.w, a2.w);
                a3.x = fmaf(xs3, wv.x, a3.x); a3.y = fmaf(xs3, wv.y, a3.y);
                a3.z = fmaf(xs3, wv.z, a3.z); a3.w = fmaf(xs3, wv.w, a3.w);
            }
        }
        if (st < 7) cp_async_wait0();
        __syncthreads();
    }
    // (last loop iteration ended with __syncthreads — smem reusable)

    if (!isA){
        // ad: row-major f16 store
        int r = rb + ty*4;
        #pragma unroll
        for (int j = 0; j < 4; j++){
            float4 a = (j==0) ? a0 : (j==1) ? a1 : (j==2) ? a2 : a3;
            __half2 h01 = __floats2half2_rn(a.x, a.y);
            __half2 h23 = __floats2half2_rn(a.z, a.w);
            uint2 p;
            p.x = *reinterpret_cast<unsigned*>(&h01);
            p.y = *reinterpret_cast<unsigned*>(&h23);
            ((uint2*)(g_ad_h + (r+j)*NU))[tx] = p;
        }
    } else {
        // ae: smem transpose -> g_aeP[b][up][t] (half2 as uint)
        // staging: [32 t-rows][130 uints], row = local t, col = up
        unsigned* stg = (unsigned*)smem;     // 32*130*4 = 16.6KB < 96KB
        #pragma unroll
        for (int j = 0; j < 4; j++){
            float4 a = (j==0) ? a0 : (j==1) ? a1 : (j==2) ? a2 : a3;
            __half2 h01 = __floats2half2_rn(a.x, a.y);
            __half2 h23 = __floats2half2_rn(a.z, a.w);
            stg[(ty*4+j)*130 + 2*tx]     = *reinterpret_cast<unsigned*>(&h01);
            stg[(ty*4+j)*130 + 2*tx + 1] = *reinterpret_cast<unsigned*>(&h23);
        }
        __syncthreads();
        int b2 = rb >> 8;          // batch
        int t0 = rb & 255;         // t base within batch
        unsigned* outP = (unsigned*)(g_aeP + (size_t)b2*128*NT);
        #pragma unroll
        for (int i = 0; i < 8; i++){
            int flat = tid + i*512;       // 4096 = 128 up x 32 tl
            int up = flat >> 5;
            int tl = flat & 31;
            outP[up*NT + t0 + tl] = stg[tl*130 + up];
        }
    }
}

// ---------------------------------------------------------------------------
// K2 v5: t-in-lanes, u-sequential — NO shuffles.
// grid 512: block = (b, 4 s rows), 256 threads; thread owns t = w*32+lane.
// Per u-pair: LDG.32 ae2 (coalesced) + LDS.128 ad(4 s) + 4x(HADD2,tanh2,HFMA2).
// f16 acc flushed to f32 every 8 u-pairs. MUFU-bound ~22us.
// ---------------------------------------------------------------------------
__global__ void __launch_bounds__(256) k2_mu(const float* __restrict__ nu)
{
    __shared__ unsigned s_adP[128*4];   // [up][s] half2-as-uint, 2KB
    __shared__ unsigned s_nu[128];      // [up] half2-as-uint
    __shared__ float s_mu[4][256];
    int blk  = blockIdx.x;
    int b    = blk >> 6;              // 64 blocks per batch
    int s0   = (blk & 63) * 4;
    int lane = threadIdx.x & 31;
    int w    = threadIdx.x >> 5;
    int tid  = threadIdx.x;

    // build s_adP: [up][s] = uint at g_ad_h[(s row)][2up..2up+1]
    {
        const unsigned* adu = (const unsigned*)(g_ad_h + (b*NT + s0)*NU); // 4 rows x 128 uints
        #pragma unroll
        for (int i = 0; i < 2; i++){
            int idx = tid + i*256;        // 0..511
            int up = idx >> 2;
            int s  = idx & 3;
            s_adP[up*4 + s] = adu[s*128 + up];
        }
    }
    // build s_nu: half2(nu[2up], nu[2up+1])
    if (tid < 128){
        float2 nf = ((const float2*)nu)[tid];
        __half2 nh = __floats2half2_rn(nf.x, nf.y);
        s_nu[tid] = *reinterpret_cast<unsigned*>(&nh);
    }
    __syncthreads();

    int t = w*32 + lane;                     // 0..255
    const __half2* aeP = g_aeP + (size_t)b*128*NT;

    float accf0 = 0.f, accf1 = 0.f, accf2 = 0.f, accf3 = 0.f;
    const uint4* adP4 = (const uint4*)s_adP;
    const uint4* nu4  = (const uint4*)s_nu;

    __half2 ae_cur = aeP[t];                 // prefetch up=0
    const __half2 z2 = __float2half2_rn(0.f);

    for (int ch = 0; ch < 16; ch++){
        __half2 a20 = z2, a21 = z2, a22 = z2, a23 = z2;
        uint4 nv0 = nu4[ch*2];
        uint4 nv1 = nu4[ch*2 + 1];
        unsigned nuarr[8] = {nv0.x,nv0.y,nv0.z,nv0.w, nv1.x,nv1.y,nv1.z,nv1.w};
        #pragma unroll
        for (int i = 0; i < 8; i++){
            int up = ch*8 + i;
            __half2 e2 = ae_cur;
            if (up < 127) ae_cur = aeP[(up+1)*NT + t];
            uint4 adv = adP4[up];
            __half2 n2 = as_h2(nuarr[i]);
            a20 = __hfma2(tanh_h2(__hadd2(as_h2(adv.x), e2)), n2, a20);
            a21 = __hfma2(tanh_h2(__hadd2(as_h2(adv.y), e2)), n2, a21);
            a22 = __hfma2(tanh_h2(__hadd2(as_h2(adv.z), e2)), n2, a22);
            a23 = __hfma2(tanh_h2(__hadd2(as_h2(adv.w), e2)), n2, a23);
        }
        float2 f;
        f = __half22float2(a20); accf0 += f.x + f.y;
        f = __half22float2(a21); accf1 += f.x + f.y;
        f = __half22float2(a22); accf2 += f.x + f.y;
        f = __half22float2(a23); accf3 += f.x + f.y;
    }

    s_mu[0][t] = accf0;
    s_mu[1][t] = accf1;
    s_mu[2][t] = accf2;
    s_mu[3][t] = accf3;
    __syncthreads();

    if (w < 4){
        int s = w;
        float v[8];
        float m = -1e30f;
        #pragma unroll
        for (int j = 0; j < 8; j++){ v[j] = s_mu[s][lane + 32*j]; m = fmaxf(m, v[j]); }
        #pragma unroll
        for (int off = 16; off; off >>= 1) m = fmaxf(m, __shfl_xor_sync(0xffffffffu, m, off));
        float sum = 0.f;
        #pragma unroll
        for (int j = 0; j < 8; j++){ v[j] = __expf(v[j] - m); sum += v[j]; }
        #pragma unroll
        for (int off = 16; off; off >>= 1) sum += __shfl_xor_sync(0xffffffffu, sum, off);
        float inv = 1.0f / sum;
        float* arow = g_alphas + (b*NT + s0 + s)*NT;
        #pragma unroll
        for (int j = 0; j < 8; j++) arow[lane + 32*j] = v[j] * inv;
        if (lane == 0) g_maxmu[b*NT + s0 + s] = m;
    }
}

// ---------------------------------------------------------------------------
// K3 (unchanged, ~3us)
// ---------------------------------------------------------------------------
__global__ void __launch_bounds__(256) k3_hhat(const float* __restrict__ de)
{
    __shared__ float s_ma[256];
    __shared__ float s_red[8];
    int b = blockIdx.x;
    int tid = threadIdx.x, lane = tid & 31, w = tid >> 5;

    float v = g_maxmu[b*NT + tid];
    float m = v;
    #pragma unroll
    for (int off = 16; off; off >>= 1) m = fmaxf(m, __shfl_xor_sync(0xffffffffu, m, off));
    if (lane == 0) s_red[w] = m;
    __syncthreads();
    m = s_red[0];
    #pragma unroll
    for (int i = 1; i < 8; i++) m = fmaxf(m, s_red[i]);
    __syncthreads();

    float e = __expf(v - m);
    float psum = e;
    #pragma unroll
    for (int off = 16; off; off >>= 1) psum += __shfl_xor_sync(0xffffffffu, psum, off);
    if (lane == 0) s_red[w] = psum;
    __syncthreads();
    float tot = 0.f;
    #pragma unroll
    for (int i = 0; i < 8; i++) tot += s_red[i];
    s_ma[tid] = e / tot;
    __syncthreads();

    int d = tid;
    const float* deb = de + b*NT*ND;
    float acc = 0.f;
    #pragma unroll 4
    for (int s = 0; s < NT; s++) acc = fmaf(deb[s*ND + d], s_ma[s], acc);
    g_hhat[b*ND + d] = acc;
}

// ---------------------------------------------------------------------------
// K4 v6 (unchanged, ~14.4us — near fp32 FMA floor for this tiling)
// ---------------------------------------------------------------------------
__global__ void __launch_bounds__(256) k4_out(
    const float* __restrict__ en, const float* __restrict__ de,
    float* __restrict__ out)
{
    extern __shared__ float smem[];
    float*  s_at = smem;                        // [t][s pad 20]: 256*20 floats (20KB)
    float4* s_en = (float4*)(smem + NT*20);     // [2][64*64] float4 (2x64KB)

    int blk = blockIdx.x;
    int b   = blk >> 4;
    int s0  = (blk & 15) * 16;
    int tid = threadIdx.x;

    {
        const float* ab = g_alphas + (b*NT + s0)*NT;
        #pragma unroll
        for (int i = 0; i < 16; i++){
            int flat = tid + i*256;
            int s = flat >> 8;               // 0..15
            int t = flat & 255;
            s_at[t*20 + s] = ab[s*NT + t];
        }
    }

    const float4* en4 = (const float4*)(en + b*NT*ND);   // 16384 float4

    #pragma unroll
    for (int i = 0; i < 16; i++)
        cp_async16(&s_en[tid + i*256], &en4[tid + i*256]);
    cp_async_commit();
    cp_async_wait0();
    __syncthreads();

    int tx = tid & 63;        // d-group of 4
    int ty = tid >> 6;        // 0..3 -> s rows ty*4..ty*4+3 (warp-uniform)

    float4 c0 = make_float4(0.f,0.f,0.f,0.f);
    float4 c1 = c0, c2 = c0, c3 = c0;

    for (int st = 0; st < 4; st++){
        int cur = st & 1;
        if (st < 3){
            float4* dst = s_en + (cur^1)*4096;
            const float4* src = en4 + (st+1)*4096;
            #pragma unroll
            for (int i = 0; i < 16; i++)
                cp_async16(&dst[tid + i*256], &src[tid + i*256]);
            cp_async_commit();
        }
        const float4* est = s_en + cur*4096;
        #pragma unroll 4
        for (int j = 0; j < 64; j++){
            int t = st*64 + j;
            float4 e  = est[j*64 + tx];
            float4 xa = *(const float4*)&s_at[t*20 + ty*4];
            c0.x = fmaf(xa.x, e.x, c0.x); c0.y = fmaf(xa.x, e.y, c0.y);
            c0.z = fmaf(xa.x, e.z, c0.z); c0.w = fmaf(xa.x, e.w, c0.w);
            c1.x = fmaf(xa.y, e.x, c1.x); c1.y = fmaf(xa.y, e.y, c1.y);
            c1.z = fmaf(xa.y, e.z, c1.z); c1.w = fmaf(xa.y, e.w, c1.w);
            c2.x = fmaf(xa.z, e.x, c2.x); c2.y = fmaf(xa.z, e.y, c2.y);
            c2.z = fmaf(xa.z, e.z, c2.z); c2.w = fmaf(xa.z, e.w, c2.w);
            c3.x = fmaf(xa.w, e.x, c3.x); c3.y = fmaf(xa.w, e.y, c3.y);
            c3.z = fmaf(xa.w, e.z, c3.z); c3.w = fmaf(xa.w, e.w, c3.w);
        }
        if (st < 3) cp_async_wait0();
        __syncthreads();
    }

    float4 hh = ((const float4*)(g_hhat + b*ND))[tx];
    float4 cs_arr[4] = {c0, c1, c2, c3};

    #pragma unroll
    for (int j = 0; j < 4; j++){
        int row = b*NT + s0 + ty*4 + j;
        float4 dv = ((const float4*)(de + row*ND))[tx];
        float4 cs = cs_arr[j];
        float4* o = (float4*)(out + (size_t)row * (4*ND));
        o[0*64 + tx] = dv;
        o[1*64 + tx] = cs;
        o[2*64 + tx] = make_float4(dv.x*cs.x, dv.y*cs.y, dv.z*cs.z, dv.w*cs.w);
        o[3*64 + tx] = make_float4(dv.x*hh.x, dv.y*hh.y, dv.z*hh.z, dv.w*hh.w);
    }
}

extern "C" void kernel_launch(void* const* d_in, const int* in_sizes, int n_in,
                              void* d_out, int out_size)
{
    const float* en   = (const float*)d_in[0];
    const float* de   = (const float*)d_in[1];
    const float* w_en = (const float*)d_in[2];
    const float* w_de = (const float*)d_in[3];
    const float* nu   = (const float*)d_in[4];
    float* out = (float*)d_out;

    const int K1_SMEM = 32*ND*4 + 2*32*64*16;           // 32KB + 64KB = 98304B
    const int K4_SMEM = NT*20*4 + 2*64*64*16;           // 20KB + 128KB = 151552B
    cudaFuncSetAttribute(k1_proj, cudaFuncAttributeMaxDynamicSharedMemorySize, K1_SMEM);
    cudaFuncSetAttribute(k4_out,  cudaFuncAttributeMaxDynamicSharedMemorySize, K4_SMEM);

    k1_proj<<<128, 512, K1_SMEM>>>(en, de, w_en, w_de);
    k2_mu  <<<512, 256>>>(nu);
    k3_hhat<<<NB,  256>>>(de);
    k4_out <<<128, 256, K4_SMEM>>>(en, de, out);
}

// round 15
// speedup vs baseline: 1.0658x; 1.0658x over previous
#include <cuda_runtime.h>
#include <cuda_fp16.h>

#define NB 8
#define NT 256   // TE == TD
#define ND 256
#define NU 256

// Scratch (no allocations allowed in kernel_launch)
__device__ __half2 g_aeP[NB*128*NT];  // ae pair-interleaved transposed: [b][u/2][t]
__device__ __half  g_ad_h[NB*NT*NU];  // (B*TD, U) row-major f16
__device__ float g_alphas[NB*NT*NT];  // (B, TD, TE)
__device__ float g_maxmu[NB*NT];      // (B, TD)
__device__ float g_hhat[NB*ND];       // (B, D)

__device__ __forceinline__ __half2 tanh_h2(__half2 h){
    unsigned u = *reinterpret_cast<unsigned*>(&h);
    unsigned r;
    asm("tanh.approx.f16x2 %0, %1;" : "=r"(r) : "r"(u));
    return *reinterpret_cast<__half2*>(&r);
}
__device__ __forceinline__ __half2 as_h2(unsigned u){
    return *reinterpret_cast<__half2*>(&u);
}

__device__ __forceinline__ void cp_async16(void* smem_dst, const void* gsrc){
    unsigned sa = (unsigned)__cvta_generic_to_shared(smem_dst);
    asm volatile("cp.async.cg.shared.global [%0], [%1], 16;\n" :: "r"(sa), "l"(gsrc));
}
__device__ __forceinline__ void cp_async_commit(){ asm volatile("cp.async.commit_group;\n" ::: "memory"); }
__device__ __forceinline__ void cp_async_wait0(){ asm volatile("cp.async.wait_group 0;\n" ::: "memory"); }

// ---------------------------------------------------------------------------
// K1 v7 (unchanged): ae = en @ w_en, ad = de @ w_de. Compute f32.
// ae -> g_aeP [b][up][t] (half2, smem-transposed); ad -> row-major f16.
// ---------------------------------------------------------------------------
__global__ void __launch_bounds__(512) k1_proj(
    const float* __restrict__ en, const float* __restrict__ de,
    const float* __restrict__ w_en, const float* __restrict__ w_de)
{
    extern __shared__ float smem[];
    float*  s_in = smem;                       // 32 rows x 256 = 8192 floats (32KB)
    float4* s_w  = (float4*)(smem + 32*ND);    // [2][32*64] float4 (2x32KB)

    int bb = blockIdx.x;
    bool isA = bb < 64;
    int rb = (isA ? bb : bb - 64) * 32;            // row base in [0,2048)
    const float* in = isA ? en : de;
    const float* w  = isA ? w_en : w_de;
    int tid = threadIdx.x;

    {
        const float4* in4 = (const float4*)(in + rb*ND);
        const float4* w4  = (const float4*)w;
        #pragma unroll
        for (int i = 0; i < 4; i++)
            cp_async16(&((float4*)s_in)[tid + i*512], &in4[tid + i*512]);
        #pragma unroll
        for (int i = 0; i < 4; i++)
            cp_async16(&s_w[tid + i*512], &w4[tid + i*512]);
        cp_async_commit();
        cp_async_wait0();
    }
    __syncthreads();

    const float4* w4 = (const float4*)w;     // flat [d*64 + ug]
    int tx = tid & 63;        // u-group of 4
    int ty = tid >> 6;        // 0..7 -> rows ty*4..ty*4+3 (warp-uniform)
    const float* srow = s_in + ty*4*ND;

    float4 a0 = make_float4(0.f,0.f,0.f,0.f);
    float4 a1 = a0, a2 = a0, a3 = a0;

    for (int st = 0; st < 8; st++){
        int cur = st & 1;
        if (st < 7){
            float4* dst = s_w + (cur^1)*2048;
            const float4* src = w4 + (st+1)*2048;
            #pragma unroll
            for (int i = 0; i < 4; i++)
                cp_async16(&dst[tid + i*512], &src[tid + i*512]);
            cp_async_commit();
        }
        const float4* wst = s_w + cur*2048;
        #pragma unroll 2
        for (int dg = 0; dg < 8; dg++){          // 8 groups of 4 d
            int dbase = st*32 + dg*4;
            float4 x0 = *(const float4*)&srow[0*ND + dbase];
            float4 x1 = *(const float4*)&srow[1*ND + dbase];
            float4 x2 = *(const float4*)&srow[2*ND + dbase];
            float4 x3 = *(const float4*)&srow[3*ND + dbase];
            #pragma unroll
            for (int jj = 0; jj < 4; jj++){
                float4 wv = wst[(dg*4 + jj)*64 + tx];
                float xs0 = (&x0.x)[jj];
                float xs1 = (&x1.x)[jj];
                float xs2 = (&x2.x)[jj];
                float xs3 = (&x3.x)[jj];
                a0.x = fmaf(xs0, wv.x, a0.x); a0.y = fmaf(xs0, wv.y, a0.y);
                a0.z = fmaf(xs0, wv.z, a0.z); a0.w = fmaf(xs0, wv.w, a0.w);
                a1.x = fmaf(xs1, wv.x, a1.x); a1.y = fmaf(xs1, wv.y, a1.y);
                a1.z = fmaf(xs1, wv.z, a1.z); a1.w = fmaf(xs1, wv.w, a1.w);
                a2.x = fmaf(xs2, wv.x, a2.x); a2.y = fmaf(xs2, wv.y, a2.y);
                a2.z = fmaf(xs2, wv.z, a2.z); a2.w = fmaf(xs2, wv.w, a2.w);
                a3.x = fmaf(xs3, wv.x, a3.x); a3.y = fmaf(xs3, wv.y, a3.y);
                a3.z = fmaf(xs3, wv.z, a3.z); a3.w = fmaf(xs3, wv.w, a3.w);
            }
        }
        if (st < 7) cp_async_wait0();
        __syncthreads();
    }
    // (last loop iteration ended with __syncthreads — smem reusable)

    if (!isA){
        int r = rb + ty*4;
        #pragma unroll
        for (int j = 0; j < 4; j++){
            float4 a = (j==0) ? a0 : (j==1) ? a1 : (j==2) ? a2 : a3;
            __half2 h01 = __floats2half2_rn(a.x, a.y);
            __half2 h23 = __floats2half2_rn(a.z, a.w);
            uint2 p;
            p.x = *reinterpret_cast<unsigned*>(&h01);
            p.y = *reinterpret_cast<unsigned*>(&h23);
            ((uint2*)(g_ad_h + (r+j)*NU))[tx] = p;
        }
    } else {
        // ae: smem transpose -> g_aeP[b][up][t] (half2 as uint)
        unsigned* stg = (unsigned*)smem;     // [32 t][130 up-cols]
        #pragma unroll
        for (int j = 0; j < 4; j++){
            float4 a = (j==0) ? a0 : (j==1) ? a1 : (j==2) ? a2 : a3;
            __half2 h01 = __floats2half2_rn(a.x, a.y);
            __half2 h23 = __floats2half2_rn(a.z, a.w);
            stg[(ty*4+j)*130 + 2*tx]     = *reinterpret_cast<unsigned*>(&h01);
            stg[(ty*4+j)*130 + 2*tx + 1] = *reinterpret_cast<unsigned*>(&h23);
        }
        __syncthreads();
        int b2 = rb >> 8;          // batch
        int t0 = rb & 255;         // t base within batch
        unsigned* outP = (unsigned*)(g_aeP + (size_t)b2*128*NT);
        #pragma unroll
        for (int i = 0; i < 8; i++){
            int flat = tid + i*512;       // 4096 = 128 up x 32 tl
            int up = flat >> 5;
            int tl = flat & 31;
            outP[up*NT + t0 + tl] = stg[tl*130 + up];
        }
    }
}

// ---------------------------------------------------------------------------
// K2 v6: t-in-lanes + ae staged via DOUBLE-BUFFERED cp.async (16-up chunks).
// Inner loop pure LDS + f16x2 math -> MUFU-bound (~20-23us).
// grid 512: block = (b, 4 s rows), 256 threads; thread owns t = tid.
// ---------------------------------------------------------------------------
__global__ void __launch_bounds__(256) k2_mu(const float* __restrict__ nu)
{
    __shared__ unsigned s_adP[128*4];      // [up][s] half2-as-uint, 2KB
    __shared__ unsigned s_nu[128];         // [up] half2-as-uint
    __shared__ unsigned s_ae[2][16*256];   // 2 x (16 up x 256 t), 2x16KB
    __shared__ float s_mu[4][256];
    int blk  = blockIdx.x;
    int b    = blk >> 6;              // 64 blocks per batch
    int s0   = (blk & 63) * 4;
    int lane = threadIdx.x & 31;
    int w    = threadIdx.x >> 5;
    int tid  = threadIdx.x;

    const unsigned* aeU = (const unsigned*)(g_aeP + (size_t)b*128*NT);  // 128 up x 256 t

    // prologue: cp.async chunk 0 (ups 0..15 = uints 0..4095)
    #pragma unroll
    for (int i = 0; i < 4; i++){
        int f16i = tid + i*256;                 // 16B unit index
        cp_async16((char*)s_ae[0] + f16i*16, (const char*)aeU + f16i*16);
    }
    cp_async_commit();

    // build s_adP: [up][s]
    {
        const unsigned* adu = (const unsigned*)(g_ad_h + (b*NT + s0)*NU); // 4 rows x 128 uints
        #pragma unroll
        for (int i = 0; i < 2; i++){
            int idx = tid + i*256;        // 0..511
            int up = idx >> 2;
            int s  = idx & 3;
            s_adP[up*4 + s] = adu[s*128 + up];
        }
    }
    // build s_nu
    if (tid < 128){
        float2 nf = ((const float2*)nu)[tid];
        __half2 nh = __floats2half2_rn(nf.x, nf.y);
        s_nu[tid] = *reinterpret_cast<unsigned*>(&nh);
    }
    cp_async_wait0();
    __syncthreads();

    int t = tid;                              // 0..255
    float accf0 = 0.f, accf1 = 0.f, accf2 = 0.f, accf3 = 0.f;
    const uint4* adP4 = (const uint4*)s_adP;
    const __half2 z2 = __float2half2_rn(0.f);

    for (int ch = 0; ch < 8; ch++){
        int cur = ch & 1;
        if (ch < 7){
            char* dst = (char*)s_ae[cur^1];
            const char* src = (const char*)aeU + (ch+1)*4096*4;
            #pragma unroll
            for (int i = 0; i < 4; i++){
                int f16i = tid + i*256;
                cp_async16(dst + f16i*16, src + f16i*16);
            }
            cp_async_commit();
        }
        __half2 a20 = z2, a21 = z2, a22 = z2, a23 = z2;
        const unsigned* ae_c = s_ae[cur];
        #pragma unroll
        for (int i = 0; i < 16; i++){
            int up = ch*16 + i;
            __half2 e2 = as_h2(ae_c[i*256 + t]);
            uint4 adv = adP4[up];
            __half2 n2 = as_h2(s_nu[up]);
            a20 = __hfma2(tanh_h2(__hadd2(as_h2(adv.x), e2)), n2, a20);
            a21 = __hfma2(tanh_h2(__hadd2(as_h2(adv.y), e2)), n2, a21);
            a22 = __hfma2(tanh_h2(__hadd2(as_h2(adv.z), e2)), n2, a22);
            a23 = __hfma2(tanh_h2(__hadd2(as_h2(adv.w), e2)), n2, a23);
        }
        float2 f;
        f = __half22float2(a20); accf0 += f.x + f.y;
        f = __half22float2(a21); accf1 += f.x + f.y;
        f = __half22float2(a22); accf2 += f.x + f.y;
        f = __half22float2(a23); accf3 += f.x + f.y;

        if (ch < 7) cp_async_wait0();
        __syncthreads();
    }

    s_mu[0][t] = accf0;
    s_mu[1][t] = accf1;
    s_mu[2][t] = accf2;
    s_mu[3][t] = accf3;
    __syncthreads();

    if (w < 4){
        int s = w;
        float v[8];
        float m = -1e30f;
        #pragma unroll
        for (int j = 0; j < 8; j++){ v[j] = s_mu[s][lane + 32*j]; m = fmaxf(m, v[j]); }
        #pragma unroll
        for (int off = 16; off; off >>= 1) m = fmaxf(m, __shfl_xor_sync(0xffffffffu, m, off));
        float sum = 0.f;
        #pragma unroll
        for (int j = 0; j < 8; j++){ v[j] = __expf(v[j] - m); sum += v[j]; }
        #pragma unroll
        for (int off = 16; off; off >>= 1) sum += __shfl_xor_sync(0xffffffffu, sum, off);
        float inv = 1.0f / sum;
        float* arow = g_alphas + (b*NT + s0 + s)*NT;
        #pragma unroll
        for (int j = 0; j < 8; j++) arow[lane + 32*j] = v[j] * inv;
        if (lane == 0) g_maxmu[b*NT + s0 + s] = m;
    }
}

// ---------------------------------------------------------------------------
// K3 (unchanged, ~3us)
// ---------------------------------------------------------------------------
__global__ void __launch_bounds__(256) k3_hhat(const float* __restrict__ de)
{
    __shared__ float s_ma[256];
    __shared__ float s_red[8];
    int b = blockIdx.x;
    int tid = threadIdx.x, lane = tid & 31, w = tid >> 5;

    float v = g_maxmu[b*NT + tid];
    float m = v;
    #pragma unroll
    for (int off = 16; off; off >>= 1) m = fmaxf(m, __shfl_xor_sync(0xffffffffu, m, off));
    if (lane == 0) s_red[w] = m;
    __syncthreads();
    m = s_red[0];
    #pragma unroll
    for (int i = 1; i < 8; i++) m = fmaxf(m, s_red[i]);
    __syncthreads();

    float e = __expf(v - m);
    float psum = e;
    #pragma unroll
    for (int off = 16; off; off >>= 1) psum += __shfl_xor_sync(0xffffffffu, psum, off);
    if (lane == 0) s_red[w] = psum;
    __syncthreads();
    float tot = 0.f;
    #pragma unroll
    for (int i = 0; i < 8; i++) tot += s_red[i];
    s_ma[tid] = e / tot;
    __syncthreads();

    int d = tid;
    const float* deb = de + b*NT*ND;
    float acc = 0.f;
    #pragma unroll 4
    for (int s = 0; s < NT; s++) acc = fmaf(deb[s*ND + d], s_ma[s], acc);
    g_hhat[b*ND + d] = acc;
}

// ---------------------------------------------------------------------------
// K4 v6 (unchanged, ~14.4us — near fp32 FMA floor for this tiling)
// ---------------------------------------------------------------------------
__global__ void __launch_bounds__(256) k4_out(
    const float* __restrict__ en, const float* __restrict__ de,
    float* __restrict__ out)
{
    extern __shared__ float smem[];
    float*  s_at = smem;                        // [t][s pad 20]: 256*20 floats (20KB)
    float4* s_en = (float4*)(smem + NT*20);     // [2][64*64] float4 (2x64KB)

    int blk = blockIdx.x;
    int b   = blk >> 4;
    int s0  = (blk & 15) * 16;
    int tid = threadIdx.x;

    {
        const float* ab = g_alphas + (b*NT + s0)*NT;
        #pragma unroll
        for (int i = 0; i < 16; i++){
            int flat = tid + i*256;
            int s = flat >> 8;               // 0..15
            int t = flat & 255;
            s_at[t*20 + s] = ab[s*NT + t];
        }
    }

    const float4* en4 = (const float4*)(en + b*NT*ND);   // 16384 float4

    #pragma unroll
    for (int i = 0; i < 16; i++)
        cp_async16(&s_en[tid + i*256], &en4[tid + i*256]);
    cp_async_commit();
    cp_async_wait0();
    __syncthreads();

    int tx = tid & 63;        // d-group of 4
    int ty = tid >> 6;        // 0..3 -> s rows ty*4..ty*4+3 (warp-uniform)

    float4 c0 = make_float4(0.f,0.f,0.f,0.f);
    float4 c1 = c0, c2 = c0, c3 = c0;

    for (int st = 0; st < 4; st++){
        int cur = st & 1;
        if (st < 3){
            float4* dst = s_en + (cur^1)*4096;
            const float4* src = en4 + (st+1)*4096;
            #pragma unroll
            for (int i = 0; i < 16; i++)
                cp_async16(&dst[tid + i*256], &src[tid + i*256]);
            cp_async_commit();
        }
        const float4* est = s_en + cur*4096;
        #pragma unroll 4
        for (int j = 0; j < 64; j++){
            int t = st*64 + j;
            float4 e  = est[j*64 + tx];
            float4 xa = *(const float4*)&s_at[t*20 + ty*4];
            c0.x = fmaf(xa.x, e.x, c0.x); c0.y = fmaf(xa.x, e.y, c0.y);
            c0.z = fmaf(xa.x, e.z, c0.z); c0.w = fmaf(xa.x, e.w, c0.w);
            c1.x = fmaf(xa.y, e.x, c1.x); c1.y = fmaf(xa.y, e.y, c1.y);
            c1.z = fmaf(xa.y, e.z, c1.z); c1.w = fmaf(xa.y, e.w, c1.w);
            c2.x = fmaf(xa.z, e.x, c2.x); c2.y = fmaf(xa.z, e.y, c2.y);
            c2.z = fmaf(xa.z, e.z, c2.z); c2.w = fmaf(xa.z, e.w, c2.w);
            c3.x = fmaf(xa.w, e.x, c3.x); c3.y = fmaf(xa.w, e.y, c3.y);
            c3.z = fmaf(xa.w, e.z, c3.z); c3.w = fmaf(xa.w, e.w, c3.w);
        }
        if (st < 3) cp_async_wait0();
        __syncthreads();
    }

    float4 hh = ((const float4*)(g_hhat + b*ND))[tx];
    float4 cs_arr[4] = {c0, c1, c2, c3};

    #pragma unroll
    for (int j = 0; j < 4; j++){
        int row = b*NT + s0 + ty*4 + j;
        float4 dv = ((const float4*)(de + row*ND))[tx];
        float4 cs = cs_arr[j];
        float4* o = (float4*)(out + (size_t)row * (4*ND));
        o[0*64 + tx] = dv;
        o[1*64 + tx] = cs;
        o[2*64 + tx] = make_float4(dv.x*cs.x, dv.y*cs.y, dv.z*cs.z, dv.w*cs.w);
        o[3*64 + tx] = make_float4(dv.x*hh.x, dv.y*hh.y, dv.z*hh.z, dv.w*hh.w);
    }
}

extern "C" void kernel_launch(void* const* d_in, const int* in_sizes, int n_in,
                              void* d_out, int out_size)
{
    const float* en   = (const float*)d_in[0];
    const float* de   = (const float*)d_in[1];
    const float* w_en = (const float*)d_in[2];
    const float* w_de = (const float*)d_in[3];
    const float* nu   = (const float*)d_in[4];
    float* out = (float*)d_out;

    const int K1_SMEM = 32*ND*4 + 2*32*64*16;           // 32KB + 64KB = 98304B
    const int K4_SMEM = NT*20*4 + 2*64*64*16;           // 20KB + 128KB = 151552B
    cudaFuncSetAttribute(k1_proj, cudaFuncAttributeMaxDynamicSharedMemorySize, K1_SMEM);
    cudaFuncSetAttribute(k4_out,  cudaFuncAttributeMaxDynamicSharedMemorySize, K4_SMEM);

    k1_proj<<<128, 512, K1_SMEM>>>(en, de, w_en, w_de);
    k2_mu  <<<512, 256>>>(nu);
    k3_hhat<<<NB,  256>>>(de);
    k4_out <<<128, 256, K4_SMEM>>>(en, de, out);
}

// round 16
// speedup vs baseline: 1.0959x; 1.0283x over previous
#include <cuda_runtime.h>
#include <cuda_fp16.h>

#define NB 8
#define NT 256   // TE == TD
#define ND 256
#define NU 256

// Scratch (no allocations allowed in kernel_launch)
__device__ unsigned g_in_u[2*262144];   // en|de rows as f16x2: [mat][row][u-pair]
__device__ unsigned g_wT_u[2*32768];    // w transposed f16x2: [mat][u][d-pair]
__device__ __half2 g_aeP[NB*128*NT];    // ae pair-interleaved transposed: [b][u/2][t]
__device__ __half  g_ad_h[NB*NT*NU];    // (B*TD, U) row-major f16
__device__ float g_alphas[NB*NT*NT];    // (B, TD, TE)
__device__ float g_maxmu[NB*NT];        // (B, TD)
__device__ float g_hhat[NB*ND];         // (B, D)

__device__ __forceinline__ __half2 tanh_h2(__half2 h){
    unsigned u = *reinterpret_cast<unsigned*>(&h);
    unsigned r;
    asm("tanh.approx.f16x2 %0, %1;" : "=r"(r) : "r"(u));
    return *reinterpret_cast<__half2*>(&r);
}
__device__ __forceinline__ __half2 as_h2(unsigned u){
    return *reinterpret_cast<__half2*>(&u);
}
__device__ __forceinline__ unsigned pack_h2(float x, float y){
    __half2 h = __floats2half2_rn(x, y);
    return *reinterpret_cast<unsigned*>(&h);
}

__device__ __forceinline__ void cp_async16(void* smem_dst, const void* gsrc){
    unsigned sa = (unsigned)__cvta_generic_to_shared(smem_dst);
    asm volatile("cp.async.cg.shared.global [%0], [%1], 16;\n" :: "r"(sa), "l"(gsrc));
}
__device__ __forceinline__ void cp_async_commit(){ asm volatile("cp.async.commit_group;\n" ::: "memory"); }
__device__ __forceinline__ void cp_async_wait0(){ asm volatile("cp.async.wait_group 0;\n" ::: "memory"); }

// ---------------------------------------------------------------------------
// K0: convert en/de rows to f16x2 and w_en/w_de to f16x2 TRANSPOSED [u][d].
// grid 640: blocks [0,512) inputs, [512,640) weight transpose tiles.
// ---------------------------------------------------------------------------
__global__ void __launch_bounds__(256) k0_convert(
    const float* __restrict__ en, const float* __restrict__ de,
    const float* __restrict__ w_en, const float* __restrict__ w_de)
{
    int blk = blockIdx.x, tid = threadIdx.x;
    if (blk < 512){
        int gtid = blk*256 + tid;            // 0..131071
        #pragma unroll
        for (int i = 0; i < 2; i++){
            int idx = gtid + i*131072;       // float2 index, 0..262143
            float2 v = ((const float2*)en)[idx];
            g_in_u[idx] = pack_h2(v.x, v.y);
            float2 u = ((const float2*)de)[idx];
            g_in_u[262144 + idx] = pack_h2(u.x, u.y);
        }
    } else {
        __shared__ float s_f[32][33];
        int wb = blk - 512;              // 0..127
        int mat = wb >> 6;               // 0: w_en, 1: w_de
        int tile = wb & 63;
        int td = (tile >> 3) * 32;       // d base
        int tu = (tile & 7) * 32;        // u base
        const float* w = mat ? w_de : w_en;
        #pragma unroll
        for (int i = 0; i < 4; i++){
            int r = (tid >> 5) + 8*i;
            int c = tid & 31;
            s_f[r][c] = w[(td + r)*256 + tu + c];
        }
        __syncthreads();
        #pragma unroll
        for (int i = 0; i < 2; i++){
            int flat = tid + 256*i;      // 0..511
            int ur = flat >> 4;          // 0..31
            int dp = flat & 15;          // 0..15
            g_wT_u[mat*32768 + (tu+ur)*128 + (td>>1) + dp] =
                pack_h2(s_f[dp*2][ur], s_f[dp*2+1][ur]);
        }
    }
}

// ---------------------------------------------------------------------------
// K1 v8 (tensor cores): ae/ad via mma.sync.m16n8k16 f16 -> f32 accum.
// grid 128: blocks [0,64) -> ae, [64,128) -> ad. Block = m128 x n64,
// warp = m16 x n64 (8 n-tiles). A frags = LDG.32 from f16 rows; B frags =
// LDG.32 from transposed w (contiguous k pairs). ae routed through smem
// transpose to g_aeP; ad stored row-major f16.
// ---------------------------------------------------------------------------
__global__ void __launch_bounds__(256) k1_mma()
{
    __shared__ unsigned s_u[32*132];     // ae transpose staging (16.9KB)
    int blk = blockIdx.x;
    bool isA = blk < 64;
    int mat = isA ? 0 : 1;
    int lb = isA ? blk : blk - 64;
    int mblk = lb >> 2;                  // 0..15  (m base = mblk*128)
    int nblk = lb & 3;                   // 0..3   (n base = nblk*64)
    int tid = threadIdx.x;
    int wid = tid >> 5, lane = tid & 31;
    int gid = lane >> 2, tig = lane & 3;
    int row0 = mblk*128 + wid*16;

    const unsigned* Au = g_in_u + mat*262144;   // [row][u-pair], 128/row
    const unsigned* Bt = g_wT_u + mat*32768;    // [u][d-pair], 128/row

    float c0[8], c1[8], c2[8], c3[8];
    #pragma unroll
    for (int j = 0; j < 8; j++){ c0[j]=0.f; c1[j]=0.f; c2[j]=0.f; c3[j]=0.f; }

    int ra  = (row0 + gid)*128;
    int rb_ = (row0 + gid + 8)*128;
    int nb0 = (nblk*64 + gid)*128;

    for (int kc = 0; kc < 16; kc++){
        int kp = kc*8 + tig;
        unsigned a0 = Au[ra  + kp];
        unsigned a1 = Au[rb_ + kp];
        unsigned a2 = Au[ra  + kp + 4];
        unsigned a3 = Au[rb_ + kp + 4];
        #pragma unroll
        for (int j = 0; j < 8; j++){
            unsigned b0 = Bt[nb0 + j*1024 + kp];
            unsigned b1 = Bt[nb0 + j*1024 + kp + 4];
            asm volatile(
                "mma.sync.aligned.m16n8k16.row.col.f32.f16.f16.f32 "
                "{%0,%1,%2,%3}, {%4,%5,%6,%7}, {%8,%9}, {%0,%1,%2,%3};"
                : "+f"(c0[j]), "+f"(c1[j]), "+f"(c2[j]), "+f"(c3[j])
                : "r"(a0), "r"(a1), "r"(a2), "r"(a3), "r"(b0), "r"(b1));
        }
    }

    if (!isA){
        // ad: row-major f16 pairs
        unsigned* outu = (unsigned*)g_ad_h;
        #pragma unroll
        for (int j = 0; j < 8; j++){
            int cp = nblk*32 + j*4 + tig;            // u-pair column
            outu[(row0+gid)*128 + cp]   = pack_h2(c0[j], c1[j]);
            outu[(row0+gid+8)*128 + cp] = pack_h2(c2[j], c3[j]);
        }
    } else {
        // ae: stage [up][t] in smem, then coalesced store to g_aeP
        #pragma unroll
        for (int j = 0; j < 8; j++){
            int up = j*4 + tig;                      // 0..31 (local u-pair)
            s_u[up*132 + wid*16 + gid]     = pack_h2(c0[j], c1[j]);
            s_u[up*132 + wid*16 + gid + 8] = pack_h2(c2[j], c3[j]);
        }
        __syncthreads();
        int b2 = mblk >> 1;
        int t0 = (mblk & 1) * 128;
        unsigned* outP = (unsigned*)g_aeP + b2*32768 + (nblk*32)*256 + t0;
        #pragma unroll
        for (int i = 0; i < 16; i++){
            int flat = tid + i*256;      // 0..4095 = 32 up x 128 t
            int up = flat >> 7;
            int tl = flat & 127;
            outP[up*256 + tl] = s_u[up*132 + tl];
        }
    }
}

// ---------------------------------------------------------------------------
// K2 v6 (unchanged): t-in-lanes + ae double-buffered via cp.async.
// ---------------------------------------------------------------------------
__global__ void __launch_bounds__(256) k2_mu(const float* __restrict__ nu)
{
    __shared__ unsigned s_adP[128*4];      // [up][s] half2-as-uint, 2KB
    __shared__ unsigned s_nu[128];         // [up] half2-as-uint
    __shared__ unsigned s_ae[2][16*256];   // 2 x (16 up x 256 t), 2x16KB
    __shared__ float s_mu[4][256];
    int blk  = blockIdx.x;
    int b    = blk >> 6;              // 64 blocks per batch
    int s0   = (blk & 63) * 4;
    int lane = threadIdx.x & 31;
    int w    = threadIdx.x >> 5;
    int tid  = threadIdx.x;

    const unsigned* aeU = (const unsigned*)(g_aeP + (size_t)b*128*NT);  // 128 up x 256 t

    #pragma unroll
    for (int i = 0; i < 4; i++){
        int f16i = tid + i*256;
        cp_async16((char*)s_ae[0] + f16i*16, (const char*)aeU + f16i*16);
    }
    cp_async_commit();

    {
        const unsigned* adu = (const unsigned*)(g_ad_h + (b*NT + s0)*NU);
        #pragma unroll
        for (int i = 0; i < 2; i++){
            int idx = tid + i*256;
            int up = idx >> 2;
            int s  = idx & 3;
            s_adP[up*4 + s] = adu[s*128 + up];
        }
    }
    if (tid < 128){
        float2 nf = ((const float2*)nu)[tid];
        __half2 nh = __floats2half2_rn(nf.x, nf.y);
        s_nu[tid] = *reinterpret_cast<unsigned*>(&nh);
    }
    cp_async_wait0();
    __syncthreads();

    int t = tid;
    float accf0 = 0.f, accf1 = 0.f, accf2 = 0.f, accf3 = 0.f;
    const uint4* adP4 = (const uint4*)s_adP;
    const __half2 z2 = __float2half2_rn(0.f);

    for (int ch = 0; ch < 8; ch++){
        int cur = ch & 1;
        if (ch < 7){
            char* dst = (char*)s_ae[cur^1];
            const char* src = (const char*)aeU + (ch+1)*4096*4;
            #pragma unroll
            for (int i = 0; i < 4; i++){
                int f16i = tid + i*256;
                cp_async16(dst + f16i*16, src + f16i*16);
            }
            cp_async_commit();
        }
        __half2 a20 = z2, a21 = z2, a22 = z2, a23 = z2;
        const unsigned* ae_c = s_ae[cur];
        #pragma unroll
        for (int i = 0; i < 16; i++){
            int up = ch*16 + i;
            __half2 e2 = as_h2(ae_c[i*256 + t]);
            uint4 adv = adP4[up];
            __half2 n2 = as_h2(s_nu[up]);
            a20 = __hfma2(tanh_h2(__hadd2(as_h2(adv.x), e2)), n2, a20);
            a21 = __hfma2(tanh_h2(__hadd2(as_h2(adv.y), e2)), n2, a21);
            a22 = __hfma2(tanh_h2(__hadd2(as_h2(adv.z), e2)), n2, a22);
            a23 = __hfma2(tanh_h2(__hadd2(as_h2(adv.w), e2)), n2, a23);
        }
        float2 f;
        f = __half22float2(a20); accf0 += f.x + f.y;
        f = __half22float2(a21); accf1 += f.x + f.y;
        f = __half22float2(a22); accf2 += f.x + f.y;
        f = __half22float2(a23); accf3 += f.x + f.y;

        if (ch < 7) cp_async_wait0();
        __syncthreads();
    }

    s_mu[0][t] = accf0;
    s_mu[1][t] = accf1;
    s_mu[2][t] = accf2;
    s_mu[3][t] = accf3;
    __syncthreads();

    if (w < 4){
        int s = w;
        float v[8];
        float m = -1e30f;
        #pragma unroll
        for (int j = 0; j < 8; j++){ v[j] = s_mu[s][lane + 32*j]; m = fmaxf(m, v[j]); }
        #pragma unroll
        for (int off = 16; off; off >>= 1) m = fmaxf(m, __shfl_xor_sync(0xffffffffu, m, off));
        float sum = 0.f;
        #pragma unroll
        for (int j = 0; j < 8; j++){ v[j] = __expf(v[j] - m); sum += v[j]; }
        #pragma unroll
        for (int off = 16; off; off >>= 1) sum += __shfl_xor_sync(0xffffffffu, sum, off);
        float inv = 1.0f / sum;
        float* arow = g_alphas + (b*NT + s0 + s)*NT;
        #pragma unroll
        for (int j = 0; j < 8; j++) arow[lane + 32*j] = v[j] * inv;
        if (lane == 0) g_maxmu[b*NT + s0 + s] = m;
    }
}

// ---------------------------------------------------------------------------
// K3 (unchanged, ~3us)
// ---------------------------------------------------------------------------
__global__ void __launch_bounds__(256) k3_hhat(const float* __restrict__ de)
{
    __shared__ float s_ma[256];
    __shared__ float s_red[8];
    int b = blockIdx.x;
    int tid = threadIdx.x, lane = tid & 31, w = tid >> 5;

    float v = g_maxmu[b*NT + tid];
    float m = v;
    #pragma unroll
    for (int off = 16; off; off >>= 1) m = fmaxf(m, __shfl_xor_sync(0xffffffffu, m, off));
    if (lane == 0) s_red[w] = m;
    __syncthreads();
    m = s_red[0];
    #pragma unroll
    for (int i = 1; i < 8; i++) m = fmaxf(m, s_red[i]);
    __syncthreads();

    float e = __expf(v - m);
    float psum = e;
    #pragma unroll
    for (int off = 16; off; off >>= 1) psum += __shfl_xor_sync(0xffffffffu, psum, off);
    if (lane == 0) s_red[w] = psum;
    __syncthreads();
    float tot = 0.f;
    #pragma unroll
    for (int i = 0; i < 8; i++) tot += s_red[i];
    s_ma[tid] = e / tot;
    __syncthreads();

    int d = tid;
    const float* deb = de + b*NT*ND;
    float acc = 0.f;
    #pragma unroll 4
    for (int s = 0; s < NT; s++) acc = fmaf(deb[s*ND + d], s_ma[s], acc);
    g_hhat[b*ND + d] = acc;
}

// ---------------------------------------------------------------------------
// K4 v6 (unchanged, ~14.4us — near fp32 FMA floor for this tiling)
// ---------------------------------------------------------------------------
__global__ void __launch_bounds__(256) k4_out(
    const float* __restrict__ en, const float* __restrict__ de,
    float* __restrict__ out)
{
    extern __shared__ float smem[];
    float*  s_at = smem;                        // [t][s pad 20]: 20KB
    float4* s_en = (float4*)(smem + NT*20);     // [2][64*64] float4 (2x64KB)

    int blk = blockIdx.x;
    int b   = blk >> 4;
    int s0  = (blk & 15) * 16;
    int tid = threadIdx.x;

    {
        const float* ab = g_alphas + (b*NT + s0)*NT;
        #pragma unroll
        for (int i = 0; i < 16; i++){
            int flat = tid + i*256;
            int s = flat >> 8;
            int t = flat & 255;
            s_at[t*20 + s] = ab[s*NT + t];
        }
    }

    const float4* en4 = (const float4*)(en + b*NT*ND);

    #pragma unroll
    for (int i = 0; i < 16; i++)
        cp_async16(&s_en[tid + i*256], &en4[tid + i*256]);
    cp_async_commit();
    cp_async_wait0();
    __syncthreads();

    int tx = tid & 63;
    int ty = tid >> 6;

    float4 c0 = make_float4(0.f,0.f,0.f,0.f);
    float4 c1 = c0, c2 = c0, c3 = c0;

    for (int st = 0; st < 4; st++){
        int cur = st & 1;
        if (st < 3){
            float4* dst = s_en + (cur^1)*4096;
            const float4* src = en4 + (st+1)*4096;
            #pragma unroll
            for (int i = 0; i < 16; i++)
                cp_async16(&dst[tid + i*256], &src[tid + i*256]);
            cp_async_commit();
        }
        const float4* est = s_en + cur*4096;
        #pragma unroll 4
        for (int j = 0; j < 64; j++){
            int t = st*64 + j;
            float4 e  = est[j*64 + tx];
            float4 xa = *(const float4*)&s_at[t*20 + ty*4];
            c0.x = fmaf(xa.x, e.x, c0.x); c0.y = fmaf(xa.x, e.y, c0.y);
            c0.z = fmaf(xa.x, e.z, c0.z); c0.w = fmaf(xa.x, e.w, c0.w);
            c1.x = fmaf(xa.y, e.x, c1.x); c1.y = fmaf(xa.y, e.y, c1.y);
            c1.z = fmaf(xa.y, e.z, c1.z); c1.w = fmaf(xa.y, e.w, c1.w);
            c2.x = fmaf(xa.z, e.x, c2.x); c2.y = fmaf(xa.z, e.y, c2.y);
            c2.z = fmaf(xa.z, e.z, c2.z); c2.w = fmaf(xa.z, e.w, c2.w);
            c3.x = fmaf(xa.w, e.x, c3.x); c3.y = fmaf(xa.w, e.y, c3.y);
            c3.z = fmaf(xa.w, e.z, c3.z); c3.w = fmaf(xa.w, e.w, c3.w);
        }
        if (st < 3) cp_async_wait0();
        __syncthreads();
    }

    float4 hh = ((const float4*)(g_hhat + b*ND))[tx];
    float4 cs_arr[4] = {c0, c1, c2, c3};

    #pragma unroll
    for (int j = 0; j < 4; j++){
        int row = b*NT + s0 + ty*4 + j;
        float4 dv = ((const float4*)(de + row*ND))[tx];
        float4 cs = cs_arr[j];
        float4* o = (float4*)(out + (size_t)row * (4*ND));
        o[0*64 + tx] = dv;
        o[1*64 + tx] = cs;
        o[2*64 + tx] = make_float4(dv.x*cs.x, dv.y*cs.y, dv.z*cs.z, dv.w*cs.w);
        o[3*64 + tx] = make_float4(dv.x*hh.x, dv.y*hh.y, dv.z*hh.z, dv.w*hh.w);
    }
}

extern "C" void kernel_launch(void* const* d_in, const int* in_sizes, int n_in,
                              void* d_out, int out_size)
{
    const float* en   = (const float*)d_in[0];
    const float* de   = (const float*)d_in[1];
    const float* w_en = (const float*)d_in[2];
    const float* w_de = (const float*)d_in[3];
    const float* nu   = (const float*)d_in[4];
    float* out = (float*)d_out;

    const int K4_SMEM = NT*20*4 + 2*64*64*16;           // 20KB + 128KB
    cudaFuncSetAttribute(k4_out, cudaFuncAttributeMaxDynamicSharedMemorySize, K4_SMEM);

    k0_convert<<<640, 256>>>(en, de, w_en, w_de);
    k1_mma    <<<128, 256>>>();
    k2_mu     <<<512, 256>>>(nu);
    k3_hhat   <<<NB,  256>>>(de);
    k4_out    <<<128, 256, K4_SMEM>>>(en, de, out);
}

// round 17
// speedup vs baseline: 1.2203x; 1.1135x over previous
#include <cuda_runtime.h>
#include <cuda_fp16.h>

#define NB 8
#define NT 256   // TE == TD
#define ND 256
#define NU 256

// Scratch (no allocations allowed in kernel_launch)
__device__ unsigned g_in_u[2*262144];   // en|de rows as f16x2: [mat][row][u-pair]
__device__ unsigned g_wT_u[2*32768];    // w transposed f16x2: [mat][u][d-pair]
__device__ __half2 g_aeP[NB*128*NT];    // ae pair-interleaved transposed: [b][u/2][t]
__device__ __half  g_ad_h[NB*NT*NU];    // (B*TD, U) row-major f16
__device__ float g_alphas[NB*NT*NT];    // (B, TD, TE)
__device__ float g_maxmu[NB*NT];        // (B, TD)
__device__ float g_ma[NB*NT];           // (B, TD) softmax of maxmu
__device__ float g_hpart[NB*8*ND];      // h_hat partials
__device__ float g_hhat[NB*ND];         // (B, D)

__device__ __forceinline__ __half2 tanh_h2(__half2 h){
    unsigned u = *reinterpret_cast<unsigned*>(&h);
    unsigned r;
    asm("tanh.approx.f16x2 %0, %1;" : "=r"(r) : "r"(u));
    return *reinterpret_cast<__half2*>(&r);
}
__device__ __forceinline__ __half2 as_h2(unsigned u){
    return *reinterpret_cast<__half2*>(&u);
}
__device__ __forceinline__ unsigned pack_h2(float x, float y){
    __half2 h = __floats2half2_rn(x, y);
    return *reinterpret_cast<unsigned*>(&h);
}

__device__ __forceinline__ void cp_async16(void* smem_dst, const void* gsrc){
    unsigned sa = (unsigned)__cvta_generic_to_shared(smem_dst);
    asm volatile("cp.async.cg.shared.global [%0], [%1], 16;\n" :: "r"(sa), "l"(gsrc));
}
__device__ __forceinline__ void cp_async_commit(){ asm volatile("cp.async.commit_group;\n" ::: "memory"); }
__device__ __forceinline__ void cp_async_wait0(){ asm volatile("cp.async.wait_group 0;\n" ::: "memory"); }

// ---------------------------------------------------------------------------
// K0 (unchanged): convert en/de rows to f16x2 and w to f16x2 transposed.
// ---------------------------------------------------------------------------
__global__ void __launch_bounds__(256) k0_convert(
    const float* __restrict__ en, const float* __restrict__ de,
    const float* __restrict__ w_en, const float* __restrict__ w_de)
{
    int blk = blockIdx.x, tid = threadIdx.x;
    if (blk < 512){
        int gtid = blk*256 + tid;
        #pragma unroll
        for (int i = 0; i < 2; i++){
            int idx = gtid + i*131072;
            float2 v = ((const float2*)en)[idx];
            g_in_u[idx] = pack_h2(v.x, v.y);
            float2 u = ((const float2*)de)[idx];
            g_in_u[262144 + idx] = pack_h2(u.x, u.y);
        }
    } else {
        __shared__ float s_f[32][33];
        int wb = blk - 512;
        int mat = wb >> 6;
        int tile = wb & 63;
        int td = (tile >> 3) * 32;
        int tu = (tile & 7) * 32;
        const float* w = mat ? w_de : w_en;
        #pragma unroll
        for (int i = 0; i < 4; i++){
            int r = (tid >> 5) + 8*i;
            int c = tid & 31;
            s_f[r][c] = w[(td + r)*256 + tu + c];
        }
        __syncthreads();
        #pragma unroll
        for (int i = 0; i < 2; i++){
            int flat = tid + 256*i;
            int ur = flat >> 4;
            int dp = flat & 15;
            g_wT_u[mat*32768 + (tu+ur)*128 + (td>>1) + dp] =
                pack_h2(s_f[dp*2][ur], s_f[dp*2+1][ur]);
        }
    }
}

// ---------------------------------------------------------------------------
// K1 v8 (unchanged): ae/ad via mma.sync.m16n8k16 f16 -> f32 accum.
// ---------------------------------------------------------------------------
__global__ void __launch_bounds__(256) k1_mma()
{
    __shared__ unsigned s_u[32*132];
    int blk = blockIdx.x;
    bool isA = blk < 64;
    int mat = isA ? 0 : 1;
    int lb = isA ? blk : blk - 64;
    int mblk = lb >> 2;
    int nblk = lb & 3;
    int tid = threadIdx.x;
    int wid = tid >> 5, lane = tid & 31;
    int gid = lane >> 2, tig = lane & 3;
    int row0 = mblk*128 + wid*16;

    const unsigned* Au = g_in_u + mat*262144;
    const unsigned* Bt = g_wT_u + mat*32768;

    float c0[8], c1[8], c2[8], c3[8];
    #pragma unroll
    for (int j = 0; j < 8; j++){ c0[j]=0.f; c1[j]=0.f; c2[j]=0.f; c3[j]=0.f; }

    int ra  = (row0 + gid)*128;
    int rb_ = (row0 + gid + 8)*128;
    int nb0 = (nblk*64 + gid)*128;

    for (int kc = 0; kc < 16; kc++){
        int kp = kc*8 + tig;
        unsigned a0 = Au[ra  + kp];
        unsigned a1 = Au[rb_ + kp];
        unsigned a2 = Au[ra  + kp + 4];
        unsigned a3 = Au[rb_ + kp + 4];
        #pragma unroll
        for (int j = 0; j < 8; j++){
            unsigned b0 = Bt[nb0 + j*1024 + kp];
            unsigned b1 = Bt[nb0 + j*1024 + kp + 4];
            asm volatile(
                "mma.sync.aligned.m16n8k16.row.col.f32.f16.f16.f32 "
                "{%0,%1,%2,%3}, {%4,%5,%6,%7}, {%8,%9}, {%0,%1,%2,%3};"
                : "+f"(c0[j]), "+f"(c1[j]), "+f"(c2[j]), "+f"(c3[j])
                : "r"(a0), "r"(a1), "r"(a2), "r"(a3), "r"(b0), "r"(b1));
        }
    }

    if (!isA){
        unsigned* outu = (unsigned*)g_ad_h;
        #pragma unroll
        for (int j = 0; j < 8; j++){
            int cp = nblk*32 + j*4 + tig;
            outu[(row0+gid)*128 + cp]   = pack_h2(c0[j], c1[j]);
            outu[(row0+gid+8)*128 + cp] = pack_h2(c2[j], c3[j]);
        }
    } else {
        #pragma unroll
        for (int j = 0; j < 8; j++){
            int up = j*4 + tig;
            s_u[up*132 + wid*16 + gid]     = pack_h2(c0[j], c1[j]);
            s_u[up*132 + wid*16 + gid + 8] = pack_h2(c2[j], c3[j]);
        }
        __syncthreads();
        int b2 = mblk >> 1;
        int t0 = (mblk & 1) * 128;
        unsigned* outP = (unsigned*)g_aeP + b2*32768 + (nblk*32)*256 + t0;
        #pragma unroll
        for (int i = 0; i < 16; i++){
            int flat = tid + i*256;
            int up = flat >> 7;
            int tl = flat & 127;
            outP[up*256 + tl] = s_u[up*132 + tl];
        }
    }
}

// ---------------------------------------------------------------------------
// K2 v6 (unchanged): t-in-lanes + ae double-buffered via cp.async.
// ---------------------------------------------------------------------------
__global__ void __launch_bounds__(256) k2_mu(const float* __restrict__ nu)
{
    __shared__ unsigned s_adP[128*4];
    __shared__ unsigned s_nu[128];
    __shared__ unsigned s_ae[2][16*256];
    __shared__ float s_mu[4][256];
    int blk  = blockIdx.x;
    int b    = blk >> 6;
    int s0   = (blk & 63) * 4;
    int lane = threadIdx.x & 31;
    int w    = threadIdx.x >> 5;
    int tid  = threadIdx.x;

    const unsigned* aeU = (const unsigned*)(g_aeP + (size_t)b*128*NT);

    #pragma unroll
    for (int i = 0; i < 4; i++){
        int f16i = tid + i*256;
        cp_async16((char*)s_ae[0] + f16i*16, (const char*)aeU + f16i*16);
    }
    cp_async_commit();

    {
        const unsigned* adu = (const unsigned*)(g_ad_h + (b*NT + s0)*NU);
        #pragma unroll
        for (int i = 0; i < 2; i++){
            int idx = tid + i*256;
            int up = idx >> 2;
            int s  = idx & 3;
            s_adP[up*4 + s] = adu[s*128 + up];
        }
    }
    if (tid < 128){
        float2 nf = ((const float2*)nu)[tid];
        __half2 nh = __floats2half2_rn(nf.x, nf.y);
        s_nu[tid] = *reinterpret_cast<unsigned*>(&nh);
    }
    cp_async_wait0();
    __syncthreads();

    int t = tid;
    float accf0 = 0.f, accf1 = 0.f, accf2 = 0.f, accf3 = 0.f;
    const uint4* adP4 = (const uint4*)s_adP;
    const __half2 z2 = __float2half2_rn(0.f);

    for (int ch = 0; ch < 8; ch++){
        int cur = ch & 1;
        if (ch < 7){
            char* dst = (char*)s_ae[cur^1];
            const char* src = (const char*)aeU + (ch+1)*4096*4;
            #pragma unroll
            for (int i = 0; i < 4; i++){
                int f16i = tid + i*256;
                cp_async16(dst + f16i*16, src + f16i*16);
            }
            cp_async_commit();
        }
        __half2 a20 = z2, a21 = z2, a22 = z2, a23 = z2;
        const unsigned* ae_c = s_ae[cur];
        #pragma unroll
        for (int i = 0; i < 16; i++){
            int up = ch*16 + i;
            __half2 e2 = as_h2(ae_c[i*256 + t]);
            uint4 adv = adP4[up];
            __half2 n2 = as_h2(s_nu[up]);
            a20 = __hfma2(tanh_h2(__hadd2(as_h2(adv.x), e2)), n2, a20);
            a21 = __hfma2(tanh_h2(__hadd2(as_h2(adv.y), e2)), n2, a21);
            a22 = __hfma2(tanh_h2(__hadd2(as_h2(adv.z), e2)), n2, a22);
            a23 = __hfma2(tanh_h2(__hadd2(as_h2(adv.w), e2)), n2, a23);
        }
        float2 f;
        f = __half22float2(a20); accf0 += f.x + f.y;
        f = __half22float2(a21); accf1 += f.x + f.y;
        f = __half22float2(a22); accf2 += f.x + f.y;
        f = __half22float2(a23); accf3 += f.x + f.y;

        if (ch < 7) cp_async_wait0();
        __syncthreads();
    }

    s_mu[0][t] = accf0;
    s_mu[1][t] = accf1;
    s_mu[2][t] = accf2;
    s_mu[3][t] = accf3;
    __syncthreads();

    if (w < 4){
        int s = w;
        float v[8];
        float m = -1e30f;
        #pragma unroll
        for (int j = 0; j < 8; j++){ v[j] = s_mu[s][lane + 32*j]; m = fmaxf(m, v[j]); }
        #pragma unroll
        for (int off = 16; off; off >>= 1) m = fmaxf(m, __shfl_xor_sync(0xffffffffu, m, off));
        float sum = 0.f;
        #pragma unroll
        for (int j = 0; j < 8; j++){ v[j] = __expf(v[j] - m); sum += v[j]; }
        #pragma unroll
        for (int off = 16; off; off >>= 1) sum += __shfl_xor_sync(0xffffffffu, sum, off);
        float inv = 1.0f / sum;
        float* arow = g_alphas + (b*NT + s0 + s)*NT;
        #pragma unroll
        for (int j = 0; j < 8; j++) arow[lane + 32*j] = v[j] * inv;
        if (lane == 0) g_maxmu[b*NT + s0 + s] = m;
    }
}

// ---------------------------------------------------------------------------
// K3a: softmax over s of max_mu[b,:] -> g_ma. grid 8.
// ---------------------------------------------------------------------------
__global__ void __launch_bounds__(256) k3a_softmax()
{
    __shared__ float s_red[8];
    int b = blockIdx.x;
    int tid = threadIdx.x, lane = tid & 31, w = tid >> 5;

    float v = g_maxmu[b*NT + tid];
    float m = v;
    #pragma unroll
    for (int off = 16; off; off >>= 1) m = fmaxf(m, __shfl_xor_sync(0xffffffffu, m, off));
    if (lane == 0) s_red[w] = m;
    __syncthreads();
    m = s_red[0];
    #pragma unroll
    for (int i = 1; i < 8; i++) m = fmaxf(m, s_red[i]);
    __syncthreads();

    float e = __expf(v - m);
    float psum = e;
    #pragma unroll
    for (int off = 16; off; off >>= 1) psum += __shfl_xor_sync(0xffffffffu, psum, off);
    if (lane == 0) s_red[w] = psum;
    __syncthreads();
    float tot = 0.f;
    #pragma unroll
    for (int i = 0; i < 8; i++) tot += s_red[i];
    g_ma[b*NT + tid] = e / tot;
}

// ---------------------------------------------------------------------------
// K3b: partial h_hat. grid 64 = (b, s-chunk of 32). Thread d, coalesced
// de loads, unroll-8 MLP.
// ---------------------------------------------------------------------------
__global__ void __launch_bounds__(256) k3b_hpart(const float* __restrict__ de)
{
    int blk = blockIdx.x;
    int b   = blk >> 3;
    int s0  = (blk & 7) * 32;
    int d   = threadIdx.x;
    const float* deb = de + (b*NT + s0)*ND;
    const float* mab = g_ma + b*NT + s0;

    float acc = 0.f;
    #pragma unroll 8
    for (int j = 0; j < 32; j++)
        acc = fmaf(deb[j*ND + d], mab[j], acc);
    g_hpart[blk*ND + d] = acc;
}

// ---------------------------------------------------------------------------
// K3c: reduce 8 partials -> g_hhat. grid 8.
// ---------------------------------------------------------------------------
__global__ void __launch_bounds__(256) k3c_hred()
{
    int b = blockIdx.x;
    int d = threadIdx.x;
    float a = 0.f;
    #pragma unroll
    for (int i = 0; i < 8; i++)
        a += g_hpart[(b*8 + i)*ND + d];
    g_hhat[b*ND + d] = a;
}

// ---------------------------------------------------------------------------
// K4 v6 (unchanged, ~14.4us)
// ---------------------------------------------------------------------------
__global__ void __launch_bounds__(256) k4_out(
    const float* __restrict__ en, const float* __restrict__ de,
    float* __restrict__ out)
{
    extern __shared__ float smem[];
    float*  s_at = smem;                        // [t][s pad 20]: 20KB
    float4* s_en = (float4*)(smem + NT*20);     // [2][64*64] float4 (2x64KB)

    int blk = blockIdx.x;
    int b   = blk >> 4;
    int s0  = (blk & 15) * 16;
    int tid = threadIdx.x;

    {
        const float* ab = g_alphas + (b*NT + s0)*NT;
        #pragma unroll
        for (int i = 0; i < 16; i++){
            int flat = tid + i*256;
            int s = flat >> 8;
            int t = flat & 255;
            s_at[t*20 + s] = ab[s*NT + t];
        }
    }

    const float4* en4 = (const float4*)(en + b*NT*ND);

    #pragma unroll
    for (int i = 0; i < 16; i++)
        cp_async16(&s_en[tid + i*256], &en4[tid + i*256]);
    cp_async_commit();
    cp_async_wait0();
    __syncthreads();

    int tx = tid & 63;
    int ty = tid >> 6;

    float4 c0 = make_float4(0.f,0.f,0.f,0.f);
    float4 c1 = c0, c2 = c0, c3 = c0;

    for (int st = 0; st < 4; st++){
        int cur = st & 1;
        if (st < 3){
            float4* dst = s_en + (cur^1)*4096;
            const float4* src = en4 + (st+1)*4096;
            #pragma unroll
            for (int i = 0; i < 16; i++)
                cp_async16(&dst[tid + i*256], &src[tid + i*256]);
            cp_async_commit();
        }
        const float4* est = s_en + cur*4096;
        #pragma unroll 4
        for (int j = 0; j < 64; j++){
            int t = st*64 + j;
            float4 e  = est[j*64 + tx];
            float4 xa = *(const float4*)&s_at[t*20 + ty*4];
            c0.x = fmaf(xa.x, e.x, c0.x); c0.y = fmaf(xa.x, e.y, c0.y);
            c0.z = fmaf(xa.x, e.z, c0.z); c0.w = fmaf(xa.x, e.w, c0.w);
            c1.x = fmaf(xa.y, e.x, c1.x); c1.y = fmaf(xa.y, e.y, c1.y);
            c1.z = fmaf(xa.y, e.z, c1.z); c1.w = fmaf(xa.y, e.w, c1.w);
            c2.x = fmaf(xa.z, e.x, c2.x); c2.y = fmaf(xa.z, e.y, c2.y);
            c2.z = fmaf(xa.z, e.z, c2.z); c2.w = fmaf(xa.z, e.w, c2.w);
            c3.x = fmaf(xa.w, e.x, c3.x); c3.y = fmaf(xa.w, e.y, c3.y);
            c3.z = fmaf(xa.w, e.z, c3.z); c3.w = fmaf(xa.w, e.w, c3.w);
        }
        if (st < 3) cp_async_wait0();
        __syncthreads();
    }

    float4 hh = ((const float4*)(g_hhat + b*ND))[tx];
    float4 cs_arr[4] = {c0, c1, c2, c3};

    #pragma unroll
    for (int j = 0; j < 4; j++){
        int row = b*NT + s0 + ty*4 + j;
        float4 dv = ((const float4*)(de + row*ND))[tx];
        float4 cs = cs_arr[j];
        float4* o = (float4*)(out + (size_t)row * (4*ND));
        o[0*64 + tx] = dv;
        o[1*64 + tx] = cs;
        o[2*64 + tx] = make_float4(dv.x*cs.x, dv.y*cs.y, dv.z*cs.z, dv.w*cs.w);
        o[3*64 + tx] = make_float4(dv.x*hh.x, dv.y*hh.y, dv.z*hh.z, dv.w*hh.w);
    }
}

extern "C" void kernel_launch(void* const* d_in, const int* in_sizes, int n_in,
                              void* d_out, int out_size)
{
    const float* en   = (const float*)d_in[0];
    const float* de   = (const float*)d_in[1];
    const float* w_en = (const float*)d_in[2];
    const float* w_de = (const float*)d_in[3];
    const float* nu   = (const float*)d_in[4];
    float* out = (float*)d_out;

    const int K4_SMEM = NT*20*4 + 2*64*64*16;           // 20KB + 128KB
    cudaFuncSetAttribute(k4_out, cudaFuncAttributeMaxDynamicSharedMemorySize, K4_SMEM);

    k0_convert<<<640, 256>>>(en, de, w_en, w_de);
    k1_mma    <<<128, 256>>>();
    k2_mu     <<<512, 256>>>(nu);
    k3a_softmax<<<NB, 256>>>();
    k3b_hpart <<<64,  256>>>(de);
    k3c_hred  <<<NB,  256>>>();
    k4_out    <<<128, 256, K4_SMEM>>>(en, de, out);
}